// round 2
// baseline (speedup 1.0000x reference)
#include <cuda_runtime.h>
#include <math.h>

// ---------------- problem constants ----------------
constexpr int B_  = 4, C_ = 21, D_ = 300, H_ = 144, W_ = 144;
constexpr int HW_ = H_ * W_;              // 20736
constexpr int NT  = B_ * HW_;             // 82944  (multiple of 128)
constexpr int HO  = 142, WO = 142;
constexpr int HWO = HO * WO;              // 20164
constexpr int NH  = B_ * HWO;             // 80656
constexpr int NHP = 632 * 128;            // 80896 padded for 128-wide GEMM tiles
constexpr int KC  = 2700;                 // 300*9 im2col K
constexpr int KCP = 2704;
constexpr long long N300 = (long long)D_ * NT;  // 24,883,200

// ---------------- scratch (__device__ globals; allocation-free kernel_launch) --------
__device__ float g_E  [1800u * 82944u];   // 6 encoder outputs stacked: we1,we2,wfy1,wiy1,wfy2,wiy2
__device__ float g_G  [900u  * 82944u];   // stacked gate GEMM output: d,f,i
__device__ float g_c12[300u  * 82944u];
__device__ float g_x12[300u  * 82944u];
__device__ float g_xt1[300u  * 82944u];
__device__ float g_ct1[300u  * 82944u];
__device__ float g_Yx [21u   * 82944u];   // repacked input
__device__ float g_IM [2700ull * 80896ull]; // im2col (pad cols stay 0)
__device__ float g_H1 [128u  * 80896u];
__device__ float g_H2 [128u  * 80896u];
__device__ float g_Wenc[1800 * 24];
__device__ float g_benc[1800];
__device__ float g_W2p [900 * 304];
__device__ float g_b2p [900];
__device__ float g_W1p [900 * 304];
__device__ float g_b1p [900];
__device__ float g_Wl1 [128 * 2704];

// ---------------- device math ----------------
__device__ __forceinline__ float gelu_f(float x) {
    return 0.5f * x * (1.0f + erff(x * 0.70710678118654752440f));
}
__device__ __forceinline__ float sigm_f(float x) {
    return 1.0f / (1.0f + expf(-x));
}

// packed f32x2 fma: d.lo += a.lo*b.lo ; d.hi += a.hi*b.hi
__device__ __forceinline__ void ffma2(unsigned long long &d,
                                      unsigned long long a,
                                      unsigned long long b) {
    asm("fma.rn.f32x2 %0, %1, %2, %0;" : "+l"(d) : "l"(a), "l"(b));
}
__device__ __forceinline__ float2 u2f(unsigned long long v) {
    float2 f;
    asm("mov.b64 {%0, %1}, %2;" : "=f"(f.x), "=f"(f.y) : "l"(v));
    return f;
}

// ---------------- pack kernels ----------------
__global__ void pack_enc(const float* __restrict__ w0, const float* __restrict__ w1,
                         const float* __restrict__ w2, const float* __restrict__ w3,
                         const float* __restrict__ w4, const float* __restrict__ w5,
                         const float* __restrict__ b0, const float* __restrict__ b1,
                         const float* __restrict__ b2, const float* __restrict__ b3,
                         const float* __restrict__ b4, const float* __restrict__ b5,
                         float* __restrict__ Wout, float* __restrict__ bout)
{
    const float* ws[6] = {w0, w1, w2, w3, w4, w5};
    const float* bs[6] = {b0, b1, b2, b3, b4, b5};
    int idx = blockIdx.x * blockDim.x + threadIdx.x;
    if (idx < 1800 * 24) {
        int m = idx / 24, k = idx % 24;
        int s = m / 300, r = m % 300;
        Wout[idx] = (k < 21) ? ws[s][r * 21 + k] : 0.0f;
    }
    if (idx < 1800) {
        int s = idx / 300, r = idx % 300;
        bout[idx] = bs[s][r];
    }
}

__global__ void pack_rec(const float* __restrict__ wd, const float* __restrict__ wf,
                         const float* __restrict__ wi,
                         const float* __restrict__ bd, const float* __restrict__ bf,
                         const float* __restrict__ bi,
                         float* __restrict__ Wout, float* __restrict__ bout)
{
    const float* ws[3] = {wd, wf, wi};
    const float* bs[3] = {bd, bf, bi};
    int idx = blockIdx.x * blockDim.x + threadIdx.x;
    if (idx < 900 * 304) {
        int m = idx / 304, k = idx % 304;
        int s = m / 300, r = m % 300;
        Wout[idx] = (k < 300) ? ws[s][r * 300 + k] : 0.0f;
    }
    if (idx < 900) {
        int s = idx / 300, r = idx % 300;
        bout[idx] = bs[s][r];
    }
}

__global__ void pack_line1(const float* __restrict__ w, float* __restrict__ Wout)
{
    int idx = blockIdx.x * blockDim.x + threadIdx.x;
    if (idx < 128 * KCP) {
        int oc = idx / KCP, k = idx % KCP;
        Wout[idx] = (k < KC) ? w[oc * KC + k] : 0.0f;
    }
}

__global__ void repack_y(const float* __restrict__ y, float* __restrict__ Yx)
{
    int idx = blockIdx.x * blockDim.x + threadIdx.x;
    if (idx < 21 * NT) {
        int k = idx / NT, n = idx % NT;
        int b = n / HW_, p = n % HW_;
        Yx[idx] = y[(b * 21 + k) * HW_ + p];
    }
}

// ---------------- GEMM: Y = gelu(W @ X + b) via packed f32x2 FMA ----------------
// W[M][Kpad] (Kpad%8==0, zero-padded), X[Kreal][N] (N%128==0), Y[M][N]
// Block tile 128x128, 256 threads, thread tile 8x8, FFMA2 inner loop.
#define BKK 8

__global__ void __launch_bounds__(256, 2)
gemm_gelu2(const float* __restrict__ W, const float* __restrict__ bias,
           const float* __restrict__ X, float* __restrict__ Y,
           int M, int Kpad, int Kreal, int N)
{
    __shared__ float Ws2[BKK][256];   // A duplicated: Ws2[k][2m]=Ws2[k][2m+1]=W[m0+m][k]
    __shared__ float Xs [BKK][128];

    int tid = threadIdx.x;
    int m0  = blockIdx.y * 128;
    long long n0 = (long long)blockIdx.x * 128;

    int wrow = tid >> 1;            // 0..127
    int wcol = (tid & 1) << 2;      // 0 or 4
    int xrow = tid >> 5;            // 0..7
    int xcol = (tid & 31) << 2;     // 0..124

    int tx = tid & 15;              // j = tx*4 + 64*sub
    int ty = tid >> 4;              // i0 = ty*8
    int i0 = ty << 3;

    const float* Xp = X + (long long)xrow * N + n0 + xcol;
    const float* Wp = W + (long long)(m0 + wrow) * Kpad + wcol;
    bool wok = (m0 + wrow) < M;

    unsigned long long acc[8][4];
#pragma unroll
    for (int i = 0; i < 8; i++)
#pragma unroll
        for (int j = 0; j < 4; j++) acc[i][j] = 0ull;

    for (int k0 = 0; k0 < Kpad; k0 += BKK) {
        float4 wv = make_float4(0.f, 0.f, 0.f, 0.f);
        if (wok) wv = *(const float4*)(Wp + k0);
        float4 xv = make_float4(0.f, 0.f, 0.f, 0.f);
        if (k0 + xrow < Kreal) xv = *(const float4*)(Xp + (long long)k0 * N);

        __syncthreads();
        *(float2*)&Ws2[wcol + 0][2 * wrow] = make_float2(wv.x, wv.x);
        *(float2*)&Ws2[wcol + 1][2 * wrow] = make_float2(wv.y, wv.y);
        *(float2*)&Ws2[wcol + 2][2 * wrow] = make_float2(wv.z, wv.z);
        *(float2*)&Ws2[wcol + 3][2 * wrow] = make_float2(wv.w, wv.w);
        *(float4*)&Xs[xrow][xcol] = xv;
        __syncthreads();

#pragma unroll
        for (int kk = 0; kk < BKK; kk++) {
            ulonglong2 A0 = *(const ulonglong2*)&Ws2[kk][2 * i0];
            ulonglong2 A1 = *(const ulonglong2*)&Ws2[kk][2 * i0 + 4];
            ulonglong2 A2 = *(const ulonglong2*)&Ws2[kk][2 * i0 + 8];
            ulonglong2 A3 = *(const ulonglong2*)&Ws2[kk][2 * i0 + 12];
            ulonglong2 B0 = *(const ulonglong2*)&Xs[kk][tx * 4];
            ulonglong2 B1 = *(const ulonglong2*)&Xs[kk][64 + tx * 4];
            unsigned long long a[8] = {A0.x, A0.y, A1.x, A1.y, A2.x, A2.y, A3.x, A3.y};
#pragma unroll
            for (int i = 0; i < 8; i++) {
                ffma2(acc[i][0], a[i], B0.x);
                ffma2(acc[i][1], a[i], B0.y);
                ffma2(acc[i][2], a[i], B1.x);
                ffma2(acc[i][3], a[i], B1.y);
            }
        }
    }

#pragma unroll
    for (int i = 0; i < 8; i++) {
        int gm = m0 + i0 + i;
        if (gm < M) {
            float bb = bias[gm];
            float* yr = Y + (long long)gm * N + n0;
            float2 p0 = u2f(acc[i][0]), p1 = u2f(acc[i][1]);
            float2 p2 = u2f(acc[i][2]), p3 = u2f(acc[i][3]);
            float4 r0, r1;
            r0.x = gelu_f(p0.x + bb); r0.y = gelu_f(p0.y + bb);
            r0.z = gelu_f(p1.x + bb); r0.w = gelu_f(p1.y + bb);
            r1.x = gelu_f(p2.x + bb); r1.y = gelu_f(p2.y + bb);
            r1.z = gelu_f(p3.x + bb); r1.w = gelu_f(p3.y + bb);
            *(float4*)(yr + tx * 4)      = r0;
            *(float4*)(yr + 64 + tx * 4) = r1;
        }
    }
}

// ---------------- elementwise gate kernels ----------------
__global__ void init_ew(const float* __restrict__ E, float* __restrict__ c12,
                        float* __restrict__ x12, float* __restrict__ xt1)
{
    long long i = (long long)blockIdx.x * blockDim.x + threadIdx.x;
    if (i >= N300) return;
    float we1  = E[i];
    float wiy1 = E[i + 900LL * NT];
    float c = sigm_f(wiy1) * (-we1);
    c12[i] = c;
    x12[i] = fmaxf(c, 0.0f);
    xt1[i] = 0.0f;
}

// gates '2': ct1 = c12*sig(gf+ywfy2) + (ywe2 + xt1 - gd)*sig(gi+ywiy2); xt1 = relu(ct1)
__global__ void stepA_ew(const float* __restrict__ E, const float* __restrict__ G,
                         const float* __restrict__ c12, float* __restrict__ xt1,
                         float* __restrict__ ct1)
{
    long long i = (long long)blockIdx.x * blockDim.x + threadIdx.x;
    if (i >= N300) return;
    float gd = G[i], gf = G[i + N300], gi = G[i + 2 * N300];
    float f  = sigm_f(gf + E[i + 1200LL * NT]);
    float t  = sigm_f(gi + E[i + 1500LL * NT]);
    float ctl = E[i + 300LL * NT] + xt1[i] - gd;
    float c = c12[i] * f + ctl * t;
    ct1[i] = c;
    xt1[i] = fmaxf(c, 0.0f);
}

// gates '1': ct2 = ct1*sig(gf+ywfy1) + (ywe1 + xt1 - gd)*sig(gi+ywiy1); c12=ct2; x12=relu
__global__ void stepB_ew(const float* __restrict__ E, const float* __restrict__ G,
                         const float* __restrict__ ct1, const float* __restrict__ xt1,
                         float* __restrict__ c12, float* __restrict__ x12)
{
    long long i = (long long)blockIdx.x * blockDim.x + threadIdx.x;
    if (i >= N300) return;
    float gd = G[i], gf = G[i + N300], gi = G[i + 2 * N300];
    float f  = sigm_f(gf + E[i + 600LL * NT]);
    float t  = sigm_f(gi + E[i + 900LL * NT]);
    float ctl = E[i] + xt1[i] - gd;
    float c = ct1[i] * f + ctl * t;
    c12[i] = c;
    x12[i] = fmaxf(c, 0.0f);
}

// ---------------- im2col for 3x3 valid conv ----------------
__global__ void im2col_k(const float* __restrict__ xt1, float* __restrict__ IM)
{
    long long idx = (long long)blockIdx.x * blockDim.x + threadIdx.x;
    if (idx >= (long long)KC * NH) return;
    int k = (int)(idx / NH);
    int n = (int)(idx % NH);
    int c  = k / 9, r = k % 9, di = r / 3, dj = r % 3;
    int b  = n / HWO, q = n % HWO, i = q / WO, j = q % WO;
    IM[(long long)k * NHP + n] =
        xt1[(long long)c * NT + b * HW_ + (i + di) * W_ + (j + dj)];
}

// ---------------- final 128 -> 1 head ----------------
__global__ void head_out(const float* __restrict__ H2, const float* __restrict__ w3,
                         const float* __restrict__ b3, float* __restrict__ out)
{
    int n = blockIdx.x * blockDim.x + threadIdx.x;
    if (n >= NH) return;
    float s = b3[0];
#pragma unroll
    for (int c = 0; c < 128; c++) s = fmaf(w3[c], H2[(long long)c * NHP + n], s);
    out[n] = s;
}

// ---------------- launcher ----------------
extern "C" void kernel_launch(void* const* d_in, const int* in_sizes, int n_in,
                              void* d_out, int out_size)
{
    (void)in_sizes; (void)n_in; (void)out_size;
    const float* in[31];
    for (int i = 0; i < 31; i++) in[i] = (const float*)d_in[i];

    float *E, *G, *c12, *x12, *xt1, *ct1, *Yx, *IM, *H1, *H2;
    float *Wenc, *benc, *W2p, *b2p, *W1p, *b1p, *Wl1;
    cudaGetSymbolAddress((void**)&E,   g_E);
    cudaGetSymbolAddress((void**)&G,   g_G);
    cudaGetSymbolAddress((void**)&c12, g_c12);
    cudaGetSymbolAddress((void**)&x12, g_x12);
    cudaGetSymbolAddress((void**)&xt1, g_xt1);
    cudaGetSymbolAddress((void**)&ct1, g_ct1);
    cudaGetSymbolAddress((void**)&Yx,  g_Yx);
    cudaGetSymbolAddress((void**)&IM,  g_IM);
    cudaGetSymbolAddress((void**)&H1,  g_H1);
    cudaGetSymbolAddress((void**)&H2,  g_H2);
    cudaGetSymbolAddress((void**)&Wenc, g_Wenc);
    cudaGetSymbolAddress((void**)&benc, g_benc);
    cudaGetSymbolAddress((void**)&W2p,  g_W2p);
    cudaGetSymbolAddress((void**)&b2p,  g_b2p);
    cudaGetSymbolAddress((void**)&W1p,  g_W1p);
    cudaGetSymbolAddress((void**)&b1p,  g_b1p);
    cudaGetSymbolAddress((void**)&Wl1,  g_Wl1);

    // ---- pack weights / input ----
    pack_enc<<<(1800 * 24 + 255) / 256, 256>>>(
        in[1], in[3], in[5], in[7], in[9], in[11],
        in[2], in[4], in[6], in[8], in[10], in[12], Wenc, benc);
    pack_rec<<<(900 * 304 + 255) / 256, 256>>>(
        in[15], in[21], in[23], in[16], in[22], in[24], W2p, b2p);  // wd2, wfx2, wix2
    pack_rec<<<(900 * 304 + 255) / 256, 256>>>(
        in[13], in[17], in[19], in[14], in[18], in[20], W1p, b1p);  // wd1, wfx1, wix1
    pack_line1<<<(128 * KCP + 255) / 256, 256>>>(in[25], Wl1);
    repack_y<<<(21 * NT + 255) / 256, 256>>>(in[0], Yx);

    int ewBlocks = (int)((N300 + 255) / 256);

    // ---- encoders: E = gelu(Wenc @ Yx + benc) ----
    gemm_gelu2<<<dim3(NT / 128, 15), 256>>>(Wenc, benc, Yx, E, 1800, 24, 21, NT);

    // ---- init state ----
    init_ew<<<ewBlocks, 256>>>(E, c12, x12, xt1);

    // ---- 3 full iterations + final half-step ----
    for (int it = 0; it < 3; it++) {
        gemm_gelu2<<<dim3(NT / 128, 8), 256>>>(W2p, b2p, x12, G, 900, 304, 300, NT);
        stepA_ew<<<ewBlocks, 256>>>(E, G, c12, xt1, ct1);
        gemm_gelu2<<<dim3(NT / 128, 8), 256>>>(W1p, b1p, xt1, G, 900, 304, 300, NT);
        stepB_ew<<<ewBlocks, 256>>>(E, G, ct1, xt1, c12, x12);
    }
    gemm_gelu2<<<dim3(NT / 128, 8), 256>>>(W2p, b2p, x12, G, 900, 304, 300, NT);
    stepA_ew<<<ewBlocks, 256>>>(E, G, c12, xt1, ct1);

    // ---- head ----
    long long imTot = (long long)KC * NH;
    im2col_k<<<(int)((imTot + 255) / 256), 256>>>(xt1, IM);
    gemm_gelu2<<<dim3(NHP / 128, 1), 256>>>(Wl1, in[26], IM, H1, 128, KCP, KC, NHP);
    gemm_gelu2<<<dim3(NHP / 128, 1), 256>>>(in[27], in[28], H1, H2, 128, 128, 128, NHP);
    head_out<<<(NH + 255) / 256, 256>>>(H2, in[29], in[30], (float*)d_out);
}

// round 3
// speedup vs baseline: 1.0038x; 1.0038x over previous
#include <cuda_runtime.h>
#include <math.h>

// ---------------- problem constants ----------------
constexpr int B_  = 4, C_ = 21, D_ = 300, H_ = 144, W_ = 144;
constexpr int HW_ = H_ * W_;              // 20736
constexpr int NT  = B_ * HW_;             // 82944  (multiple of 128)
constexpr int HO  = 142, WO = 142;
constexpr int HWO = HO * WO;              // 20164
constexpr int NH  = B_ * HWO;             // 80656
constexpr int NHP = 632 * 128;            // 80896 padded for 128-wide GEMM tiles
constexpr int KC  = 2700;                 // 300*9 im2col K
constexpr int KCP = 2704;
constexpr long long N300 = (long long)D_ * NT;  // 24,883,200

// ---------------- scratch (__device__ globals; allocation-free kernel_launch) --------
__device__ float g_E  [1800u * 82944u];   // 6 encoder outputs stacked: we1,we2,wfy1,wiy1,wfy2,wiy2
__device__ float g_G  [900u  * 82944u];   // stacked gate GEMM output: d,f,i
__device__ float g_c12[300u  * 82944u];
__device__ float g_x12[300u  * 82944u];
__device__ float g_xt1[300u  * 82944u];
__device__ float g_ct1[300u  * 82944u];
__device__ float g_Yx [21u   * 82944u];   // repacked input
__device__ float g_IM [2700ull * 80896ull]; // im2col (pad cols stay 0)
__device__ float g_H1 [128u  * 80896u];
__device__ float g_H2 [128u  * 80896u];
__device__ float g_Wenc[1800 * 24];
__device__ float g_benc[1800];
__device__ float g_W2p [900 * 304];
__device__ float g_b2p [900];
__device__ float g_W1p [900 * 304];
__device__ float g_b1p [900];
__device__ float g_Wl1 [128 * 2704];

// ---------------- device math ----------------
__device__ __forceinline__ float gelu_f(float x) {
    return 0.5f * x * (1.0f + erff(x * 0.70710678118654752440f));
}
__device__ __forceinline__ float sigm_f(float x) {
    return 1.0f / (1.0f + expf(-x));
}

// packed f32x2 fma: d.lo += a.lo*b.lo ; d.hi += a.hi*b.hi
__device__ __forceinline__ void ffma2(unsigned long long &d,
                                      unsigned long long a,
                                      unsigned long long b) {
    asm("fma.rn.f32x2 %0, %1, %2, %0;" : "+l"(d) : "l"(a), "l"(b));
}
__device__ __forceinline__ float2 u2f(unsigned long long v) {
    float2 f;
    asm("mov.b64 {%0, %1}, %2;" : "=f"(f.x), "=f"(f.y) : "l"(v));
    return f;
}

// ---------------- pack kernels ----------------
__global__ void pack_enc(const float* __restrict__ w0, const float* __restrict__ w1,
                         const float* __restrict__ w2, const float* __restrict__ w3,
                         const float* __restrict__ w4, const float* __restrict__ w5,
                         const float* __restrict__ b0, const float* __restrict__ b1,
                         const float* __restrict__ b2, const float* __restrict__ b3,
                         const float* __restrict__ b4, const float* __restrict__ b5,
                         float* __restrict__ Wout, float* __restrict__ bout)
{
    const float* ws[6] = {w0, w1, w2, w3, w4, w5};
    const float* bs[6] = {b0, b1, b2, b3, b4, b5};
    int idx = blockIdx.x * blockDim.x + threadIdx.x;
    if (idx < 1800 * 24) {
        int m = idx / 24, k = idx % 24;
        int s = m / 300, r = m % 300;
        Wout[idx] = (k < 21) ? ws[s][r * 21 + k] : 0.0f;
    }
    if (idx < 1800) {
        int s = idx / 300, r = idx % 300;
        bout[idx] = bs[s][r];
    }
}

__global__ void pack_rec(const float* __restrict__ wd, const float* __restrict__ wf,
                         const float* __restrict__ wi,
                         const float* __restrict__ bd, const float* __restrict__ bf,
                         const float* __restrict__ bi,
                         float* __restrict__ Wout, float* __restrict__ bout)
{
    const float* ws[3] = {wd, wf, wi};
    const float* bs[3] = {bd, bf, bi};
    int idx = blockIdx.x * blockDim.x + threadIdx.x;
    if (idx < 900 * 304) {
        int m = idx / 304, k = idx % 304;
        int s = m / 300, r = m % 300;
        Wout[idx] = (k < 300) ? ws[s][r * 300 + k] : 0.0f;
    }
    if (idx < 900) {
        int s = idx / 300, r = idx % 300;
        bout[idx] = bs[s][r];
    }
}

__global__ void pack_line1(const float* __restrict__ w, float* __restrict__ Wout)
{
    int idx = blockIdx.x * blockDim.x + threadIdx.x;
    if (idx < 128 * KCP) {
        int oc = idx / KCP, k = idx % KCP;
        Wout[idx] = (k < KC) ? w[oc * KC + k] : 0.0f;
    }
}

__global__ void repack_y(const float* __restrict__ y, float* __restrict__ Yx)
{
    int idx = blockIdx.x * blockDim.x + threadIdx.x;
    if (idx < 21 * NT) {
        int k = idx / NT, n = idx % NT;
        int b = n / HW_, p = n % HW_;
        Yx[idx] = y[(b * 21 + k) * HW_ + p];
    }
}

// ---------------- GEMM: Y = gelu(W @ X + b) via packed f32x2 FMA ----------------
// W[M][Kpad] (Kpad%8==0, zero-padded), X[Kreal][N] (N%128==0), Y[M][N]
// Block tile 128x128, 256 threads, thread tile 8x8, FFMA2 inner loop.
#define BKK 8

__global__ void __launch_bounds__(256, 2)
gemm_gelu2(const float* __restrict__ W, const float* __restrict__ bias,
           const float* __restrict__ X, float* __restrict__ Y,
           int M, int Kpad, int Kreal, int N)
{
    __shared__ float Ws2[BKK][256];   // A duplicated: Ws2[k][2m]=Ws2[k][2m+1]=W[m0+m][k]
    __shared__ float Xs [BKK][128];

    int tid = threadIdx.x;
    int m0  = blockIdx.y * 128;
    long long n0 = (long long)blockIdx.x * 128;

    int wrow = tid >> 1;            // 0..127
    int wcol = (tid & 1) << 2;      // 0 or 4
    int xrow = tid >> 5;            // 0..7
    int xcol = (tid & 31) << 2;     // 0..124

    int tx = tid & 15;              // j = tx*4 + 64*sub
    int ty = tid >> 4;              // i0 = ty*8
    int i0 = ty << 3;

    const float* Xp = X + (long long)xrow * N + n0 + xcol;
    const float* Wp = W + (long long)(m0 + wrow) * Kpad + wcol;
    bool wok = (m0 + wrow) < M;

    unsigned long long acc[8][4];
#pragma unroll
    for (int i = 0; i < 8; i++)
#pragma unroll
        for (int j = 0; j < 4; j++) acc[i][j] = 0ull;

    for (int k0 = 0; k0 < Kpad; k0 += BKK) {
        float4 wv = make_float4(0.f, 0.f, 0.f, 0.f);
        if (wok) wv = *(const float4*)(Wp + k0);
        float4 xv = make_float4(0.f, 0.f, 0.f, 0.f);
        if (k0 + xrow < Kreal) xv = *(const float4*)(Xp + (long long)k0 * N);

        __syncthreads();
        *(float2*)&Ws2[wcol + 0][2 * wrow] = make_float2(wv.x, wv.x);
        *(float2*)&Ws2[wcol + 1][2 * wrow] = make_float2(wv.y, wv.y);
        *(float2*)&Ws2[wcol + 2][2 * wrow] = make_float2(wv.z, wv.z);
        *(float2*)&Ws2[wcol + 3][2 * wrow] = make_float2(wv.w, wv.w);
        *(float4*)&Xs[xrow][xcol] = xv;
        __syncthreads();

#pragma unroll
        for (int kk = 0; kk < BKK; kk++) {
            ulonglong2 A0 = *(const ulonglong2*)&Ws2[kk][2 * i0];
            ulonglong2 A1 = *(const ulonglong2*)&Ws2[kk][2 * i0 + 4];
            ulonglong2 A2 = *(const ulonglong2*)&Ws2[kk][2 * i0 + 8];
            ulonglong2 A3 = *(const ulonglong2*)&Ws2[kk][2 * i0 + 12];
            ulonglong2 B0 = *(const ulonglong2*)&Xs[kk][tx * 4];
            ulonglong2 B1 = *(const ulonglong2*)&Xs[kk][64 + tx * 4];
            unsigned long long a[8] = {A0.x, A0.y, A1.x, A1.y, A2.x, A2.y, A3.x, A3.y};
#pragma unroll
            for (int i = 0; i < 8; i++) {
                ffma2(acc[i][0], a[i], B0.x);
                ffma2(acc[i][1], a[i], B0.y);
                ffma2(acc[i][2], a[i], B1.x);
                ffma2(acc[i][3], a[i], B1.y);
            }
        }
    }

#pragma unroll
    for (int i = 0; i < 8; i++) {
        int gm = m0 + i0 + i;
        if (gm < M) {
            float bb = bias[gm];
            float* yr = Y + (long long)gm * N + n0;
            float2 p0 = u2f(acc[i][0]), p1 = u2f(acc[i][1]);
            float2 p2 = u2f(acc[i][2]), p3 = u2f(acc[i][3]);
            float4 r0, r1;
            r0.x = gelu_f(p0.x + bb); r0.y = gelu_f(p0.y + bb);
            r0.z = gelu_f(p1.x + bb); r0.w = gelu_f(p1.y + bb);
            r1.x = gelu_f(p2.x + bb); r1.y = gelu_f(p2.y + bb);
            r1.z = gelu_f(p3.x + bb); r1.w = gelu_f(p3.y + bb);
            *(float4*)(yr + tx * 4)      = r0;
            *(float4*)(yr + 64 + tx * 4) = r1;
        }
    }
}

// ---------------- elementwise gate kernels ----------------
__global__ void init_ew(const float* __restrict__ E, float* __restrict__ c12,
                        float* __restrict__ x12, float* __restrict__ xt1)
{
    long long i = (long long)blockIdx.x * blockDim.x + threadIdx.x;
    if (i >= N300) return;
    float we1  = E[i];
    float wiy1 = E[i + 900LL * NT];
    float c = sigm_f(wiy1) * (-we1);
    c12[i] = c;
    x12[i] = fmaxf(c, 0.0f);
    xt1[i] = 0.0f;
}

// gates '2': ct1 = c12*sig(gf+ywfy2) + (ywe2 + xt1 - gd)*sig(gi+ywiy2); xt1 = relu(ct1)
__global__ void stepA_ew(const float* __restrict__ E, const float* __restrict__ G,
                         const float* __restrict__ c12, float* __restrict__ xt1,
                         float* __restrict__ ct1)
{
    long long i = (long long)blockIdx.x * blockDim.x + threadIdx.x;
    if (i >= N300) return;
    float gd = G[i], gf = G[i + N300], gi = G[i + 2 * N300];
    float f  = sigm_f(gf + E[i + 1200LL * NT]);
    float t  = sigm_f(gi + E[i + 1500LL * NT]);
    float ctl = E[i + 300LL * NT] + xt1[i] - gd;
    float c = c12[i] * f + ctl * t;
    ct1[i] = c;
    xt1[i] = fmaxf(c, 0.0f);
}

// gates '1': ct2 = ct1*sig(gf+ywfy1) + (ywe1 + xt1 - gd)*sig(gi+ywiy1); c12=ct2; x12=relu
__global__ void stepB_ew(const float* __restrict__ E, const float* __restrict__ G,
                         const float* __restrict__ ct1, const float* __restrict__ xt1,
                         float* __restrict__ c12, float* __restrict__ x12)
{
    long long i = (long long)blockIdx.x * blockDim.x + threadIdx.x;
    if (i >= N300) return;
    float gd = G[i], gf = G[i + N300], gi = G[i + 2 * N300];
    float f  = sigm_f(gf + E[i + 600LL * NT]);
    float t  = sigm_f(gi + E[i + 900LL * NT]);
    float ctl = E[i] + xt1[i] - gd;
    float c = ct1[i] * f + ctl * t;
    c12[i] = c;
    x12[i] = fmaxf(c, 0.0f);
}

// ---------------- im2col for 3x3 valid conv ----------------
__global__ void im2col_k(const float* __restrict__ xt1, float* __restrict__ IM)
{
    long long idx = (long long)blockIdx.x * blockDim.x + threadIdx.x;
    if (idx >= (long long)KC * NH) return;
    int k = (int)(idx / NH);
    int n = (int)(idx % NH);
    int c  = k / 9, r = k % 9, di = r / 3, dj = r % 3;
    int b  = n / HWO, q = n % HWO, i = q / WO, j = q % WO;
    IM[(long long)k * NHP + n] =
        xt1[(long long)c * NT + b * HW_ + (i + di) * W_ + (j + dj)];
}

// ---------------- final 128 -> 1 head ----------------
__global__ void head_out(const float* __restrict__ H2, const float* __restrict__ w3,
                         const float* __restrict__ b3, float* __restrict__ out)
{
    int n = blockIdx.x * blockDim.x + threadIdx.x;
    if (n >= NH) return;
    float s = b3[0];
#pragma unroll
    for (int c = 0; c < 128; c++) s = fmaf(w3[c], H2[(long long)c * NHP + n], s);
    out[n] = s;
}

// ---------------- launcher ----------------
extern "C" void kernel_launch(void* const* d_in, const int* in_sizes, int n_in,
                              void* d_out, int out_size)
{
    (void)in_sizes; (void)n_in; (void)out_size;
    const float* in[31];
    for (int i = 0; i < 31; i++) in[i] = (const float*)d_in[i];

    float *E, *G, *c12, *x12, *xt1, *ct1, *Yx, *IM, *H1, *H2;
    float *Wenc, *benc, *W2p, *b2p, *W1p, *b1p, *Wl1;
    cudaGetSymbolAddress((void**)&E,   g_E);
    cudaGetSymbolAddress((void**)&G,   g_G);
    cudaGetSymbolAddress((void**)&c12, g_c12);
    cudaGetSymbolAddress((void**)&x12, g_x12);
    cudaGetSymbolAddress((void**)&xt1, g_xt1);
    cudaGetSymbolAddress((void**)&ct1, g_ct1);
    cudaGetSymbolAddress((void**)&Yx,  g_Yx);
    cudaGetSymbolAddress((void**)&IM,  g_IM);
    cudaGetSymbolAddress((void**)&H1,  g_H1);
    cudaGetSymbolAddress((void**)&H2,  g_H2);
    cudaGetSymbolAddress((void**)&Wenc, g_Wenc);
    cudaGetSymbolAddress((void**)&benc, g_benc);
    cudaGetSymbolAddress((void**)&W2p,  g_W2p);
    cudaGetSymbolAddress((void**)&b2p,  g_b2p);
    cudaGetSymbolAddress((void**)&W1p,  g_W1p);
    cudaGetSymbolAddress((void**)&b1p,  g_b1p);
    cudaGetSymbolAddress((void**)&Wl1,  g_Wl1);

    // ---- pack weights / input ----
    pack_enc<<<(1800 * 24 + 255) / 256, 256>>>(
        in[1], in[3], in[5], in[7], in[9], in[11],
        in[2], in[4], in[6], in[8], in[10], in[12], Wenc, benc);
    pack_rec<<<(900 * 304 + 255) / 256, 256>>>(
        in[15], in[21], in[23], in[16], in[22], in[24], W2p, b2p);  // wd2, wfx2, wix2
    pack_rec<<<(900 * 304 + 255) / 256, 256>>>(
        in[13], in[17], in[19], in[14], in[18], in[20], W1p, b1p);  // wd1, wfx1, wix1
    pack_line1<<<(128 * KCP + 255) / 256, 256>>>(in[25], Wl1);
    repack_y<<<(21 * NT + 255) / 256, 256>>>(in[0], Yx);

    int ewBlocks = (int)((N300 + 255) / 256);

    // ---- encoders: E = gelu(Wenc @ Yx + benc) ----
    gemm_gelu2<<<dim3(NT / 128, 15), 256>>>(Wenc, benc, Yx, E, 1800, 24, 21, NT);

    // ---- init state ----
    init_ew<<<ewBlocks, 256>>>(E, c12, x12, xt1);

    // ---- 3 full iterations + final half-step ----
    for (int it = 0; it < 3; it++) {
        gemm_gelu2<<<dim3(NT / 128, 8), 256>>>(W2p, b2p, x12, G, 900, 304, 300, NT);
        stepA_ew<<<ewBlocks, 256>>>(E, G, c12, xt1, ct1);
        gemm_gelu2<<<dim3(NT / 128, 8), 256>>>(W1p, b1p, xt1, G, 900, 304, 300, NT);
        stepB_ew<<<ewBlocks, 256>>>(E, G, ct1, xt1, c12, x12);
    }
    gemm_gelu2<<<dim3(NT / 128, 8), 256>>>(W2p, b2p, x12, G, 900, 304, 300, NT);
    stepA_ew<<<ewBlocks, 256>>>(E, G, c12, xt1, ct1);

    // ---- head ----
    long long imTot = (long long)KC * NH;
    im2col_k<<<(int)((imTot + 255) / 256), 256>>>(xt1, IM);
    gemm_gelu2<<<dim3(NHP / 128, 1), 256>>>(Wl1, in[26], IM, H1, 128, KCP, KC, NHP);
    gemm_gelu2<<<dim3(NHP / 128, 1), 256>>>(in[27], in[28], H1, H2, 128, 128, 128, NHP);
    head_out<<<(NH + 255) / 256, 256>>>(H2, in[29], in[30], (float*)d_out);
}

// round 5
// speedup vs baseline: 1.8084x; 1.8015x over previous
#include <cuda_runtime.h>
#include <cuda_bf16.h>
#include <math.h>
#include <stdint.h>

constexpr int B_ = 4, H_ = 144, W_ = 144;
constexpr int HW_ = H_ * W_;        // 20736
constexpr int NT  = B_ * HW_;       // 82944 = 648*128
constexpr int HO = 142, WO = 142, HWO = HO * WO, NH = B_ * HWO;
constexpr int PXT = NT / 128;       // 648
constexpr int SE = 1920, SG = 1024, KR = 320;

// ---------- scratch ----------
__device__ float         g_E [ (size_t)NT * SE ];
__device__ float         g_G [ (size_t)NT * SG ];
__device__ float         g_c12f[(size_t)NT * KR];
__device__ float         g_ct1f[(size_t)NT * KR];
__device__ float         g_xt1f[(size_t)NT * KR];
__device__ __nv_bfloat16 g_x12h[(size_t)(NT+512) * KR], g_x12l[(size_t)(NT+512) * KR];
__device__ __nv_bfloat16 g_xt1h[(size_t)(NT+512) * KR], g_xt1l[(size_t)(NT+512) * KR];
__device__ __nv_bfloat16 g_Yxh[(size_t)NT * 64], g_Yxl[(size_t)NT * 64];
__device__ __nv_bfloat16 g_H1h[(size_t)NT * 128], g_H1l[(size_t)NT * 128];
__device__ float         g_H2 [(size_t)NT * 128];
__device__ __nv_bfloat16 g_Wench[1920 * 64], g_Wencl[1920 * 64];
__device__ __nv_bfloat16 g_W2h[1024 * 320], g_W2l[1024 * 320];
__device__ __nv_bfloat16 g_W1h[1024 * 320], g_W1l[1024 * 320];
__device__ __nv_bfloat16 g_L1h[9 * 128 * 320], g_L1l[9 * 128 * 320];
__device__ __nv_bfloat16 g_L2h[128 * 128], g_L2l[128 * 128];
__device__ float g_benc[1920], g_b2[1024], g_b1[1024];

// ---------- helpers ----------
__device__ __forceinline__ uint32_t s2u(const void* p) {
    uint32_t a;
    asm("{ .reg .u64 t; cvta.to.shared.u64 t, %1; cvt.u32.u64 %0, t; }" : "=r"(a) : "l"(p));
    return a;
}
__device__ __forceinline__ float gelu_f(float x) {
    return 0.5f * x * (1.0f + erff(x * 0.70710678118654752440f));
}
__device__ __forceinline__ float sigm_f(float x) { return 1.0f / (1.0f + expf(-x)); }
__device__ __forceinline__ void splitb(float x, __nv_bfloat16& h, __nv_bfloat16& l) {
    h = __float2bfloat16(x);
    l = __float2bfloat16(x - __bfloat162float(h));
}

__device__ __forceinline__ void ldmx4(uint32_t* r, uint32_t addr) {
    asm volatile("ldmatrix.sync.aligned.m8n8.x4.shared.b16 {%0,%1,%2,%3}, [%4];"
                 : "=r"(r[0]), "=r"(r[1]), "=r"(r[2]), "=r"(r[3]) : "r"(addr));
}
__device__ __forceinline__ void hmma(float* c, const uint32_t* a, uint32_t b0, uint32_t b1) {
    asm volatile("mma.sync.aligned.m16n8k16.row.col.f32.bf16.bf16.f32 "
                 "{%0,%1,%2,%3}, {%4,%5,%6,%7}, {%8,%9}, {%0,%1,%2,%3};"
                 : "+f"(c[0]), "+f"(c[1]), "+f"(c[2]), "+f"(c[3])
                 : "r"(a[0]), "r"(a[1]), "r"(a[2]), "r"(a[3]), "r"(b0), "r"(b1));
}

// ================= generic tiled MMA GEMM (bf16x3, mma.sync) =================
// D[128px][128ch] = sum over taps,chunks of A[px+tapOff][k] * B[tap*128+ch][k]
// A rows stride kpad (bf16), B rows stride kpad. chunk K=32, double-buffered.
// smem: 2 stages x 4 matrices (Ah,Al,Bh,Bl) x (128 rows x 80B pitch) = 81920B
__global__ void __launch_bounds__(512, 1)
mma_gemm(const __nv_bfloat16* __restrict__ Ah, const __nv_bfloat16* __restrict__ Al,
         const __nv_bfloat16* __restrict__ Bh, const __nv_bfloat16* __restrict__ Bl,
         const float* __restrict__ bias,
         float* __restrict__ outf, __nv_bfloat16* __restrict__ outh, __nv_bfloat16* __restrict__ outl,
         int kpad, int nchunks, int ntaps, int conv, int ostride, int mode)
{
    extern __shared__ char smem[];
    const uint32_t sb = s2u(smem);
    const int tid = threadIdx.x;
    const int lane = tid & 31, warp = tid >> 5;
    const int wm = warp >> 2, wn = warp & 3;
    const int ch0 = blockIdx.x * 128;
    const int n0  = blockIdx.y * 128;

    const int ldRow = tid >> 2, ldC = tid & 3;

    // ldmatrix lane address pieces (stage-relative)
    const uint32_t aOff = (uint32_t)((wm * 32 + (lane & 15)) * 80 + (lane >> 4) * 16);
    const uint32_t bOff = (uint32_t)((wn * 32 + ((lane >> 4) & 1) * 8 + (lane & 7)) * 80
                                     + ((lane >> 3) & 1) * 16);

    float acc[2][4][4];
#pragma unroll
    for (int i = 0; i < 2; i++)
#pragma unroll
        for (int j = 0; j < 4; j++)
#pragma unroll
            for (int q = 0; q < 4; q++) acc[i][j][q] = 0.f;

    const int total = ntaps * nchunks;

    // ---- prologue: load chunk 0 into stage 0 ----
    {
        long long ao = (long long)(n0 + ldRow) * kpad + ldC * 8;
        long long bo = (long long)(ch0 + ldRow) * kpad + ldC * 8;
        char* st = smem + ldRow * 80 + ldC * 16;
        *(uint4*)(st        ) = *(const uint4*)(Ah + ao);
        *(uint4*)(st + 10240) = *(const uint4*)(Al + ao);
        *(uint4*)(st + 20480) = *(const uint4*)(Bh + bo);
        *(uint4*)(st + 30720) = *(const uint4*)(Bl + bo);
    }
    __syncthreads();

    for (int tc = 0; tc < total; tc++) {
        const int stage = tc & 1;
        uint4 pf[4];
        const bool more = (tc + 1) < total;
        if (more) {
            int t1 = tc + 1;
            int tap = t1 / nchunks, chunk = t1 - tap * nchunks;
            int tapOff = conv ? ((tap / 3) * 144 + (tap % 3)) : 0;
            int brow0  = conv ? tap * 128 : 0;
            long long k0 = (long long)chunk * 32;
            long long ao = (long long)(n0 + ldRow + tapOff) * kpad + k0 + ldC * 8;
            long long bo = (long long)(brow0 + ch0 + ldRow) * kpad + k0 + ldC * 8;
            pf[0] = *(const uint4*)(Ah + ao);
            pf[1] = *(const uint4*)(Al + ao);
            pf[2] = *(const uint4*)(Bh + bo);
            pf[3] = *(const uint4*)(Bl + bo);
        }

        // ---- compute this stage: 2 k16 steps ----
        const uint32_t sbase = sb + stage * 40960;
#pragma unroll
        for (int kb = 0; kb < 2; kb++) {
            uint32_t ah[2][4], al[2][4], bh[2][4], bl[2][4];
#pragma unroll
            for (int mt = 0; mt < 2; mt++) {
                uint32_t ad = sbase + kb * 32 + mt * 1280 + aOff;
                ldmx4(ah[mt], ad);
                ldmx4(al[mt], ad + 10240);
            }
#pragma unroll
            for (int np = 0; np < 2; np++) {
                uint32_t bd = sbase + 20480 + kb * 32 + np * 1280 + bOff;
                ldmx4(bh[np], bd);
                ldmx4(bl[np], bd + 10240);
            }
#pragma unroll
            for (int mt = 0; mt < 2; mt++)
#pragma unroll
                for (int nt = 0; nt < 4; nt++) {
                    const int np = nt >> 1, q = (nt & 1) * 2;
                    hmma(acc[mt][nt], ah[mt], bh[np][q], bh[np][q + 1]);
                    hmma(acc[mt][nt], ah[mt], bl[np][q], bl[np][q + 1]);
                    hmma(acc[mt][nt], al[mt], bh[np][q], bh[np][q + 1]);
                }
        }

        if (more) {
            char* st = smem + (stage ^ 1) * 40960 + ldRow * 80 + ldC * 16;
            *(uint4*)(st        ) = pf[0];
            *(uint4*)(st + 10240) = pf[1];
            *(uint4*)(st + 20480) = pf[2];
            *(uint4*)(st + 30720) = pf[3];
            __syncthreads();
        }
    }

    // ---- epilogue ----
    const int rbase = n0 + wm * 32 + (lane >> 2);
    const int cbase = ch0 + wn * 32 + (lane & 3) * 2;
#pragma unroll
    for (int mt = 0; mt < 2; mt++)
#pragma unroll
        for (int nt = 0; nt < 4; nt++) {
            const int col = cbase + nt * 8;
            const float b0 = bias[col], b1 = bias[col + 1];
#pragma unroll
            for (int half = 0; half < 2; half++) {
                const long long row = rbase + mt * 16 + half * 8;
                float v0 = gelu_f(acc[mt][nt][half * 2 + 0] + b0);
                float v1 = gelu_f(acc[mt][nt][half * 2 + 1] + b1);
                if (mode == 0) {
                    float2 v = make_float2(v0, v1);
                    *(float2*)(outf + row * ostride + col) = v;
                } else {
                    __nv_bfloat16 h0, l0, h1, l1;
                    splitb(v0, h0, l0);
                    splitb(v1, h1, l1);
                    uint32_t ph = (uint32_t)__bfloat16_as_ushort(h0) |
                                  ((uint32_t)__bfloat16_as_ushort(h1) << 16);
                    uint32_t pl = (uint32_t)__bfloat16_as_ushort(l0) |
                                  ((uint32_t)__bfloat16_as_ushort(l1) << 16);
                    *(uint32_t*)(outh + row * ostride + col) = ph;
                    *(uint32_t*)(outl + row * ostride + col) = pl;
                }
            }
        }
}

// ---------- packs ----------
__global__ void pack_encN(const float* w0, const float* w1, const float* w2,
                          const float* w3, const float* w4, const float* w5,
                          const float* b0, const float* b1, const float* b2,
                          const float* b3, const float* b4, const float* b5)
{
    int idx = blockIdx.x * blockDim.x + threadIdx.x;
    if (idx >= 1920 * 64) return;
    const float* ws[6] = {w0, w1, w2, w3, w4, w5};
    const float* bs[6] = {b0, b1, b2, b3, b4, b5};
    int r0 = idx / 64, k = idx % 64;
    float v = 0.f;
    if (r0 < 1800 && k < 21) { int s = r0 / 300, r = r0 % 300; v = ws[s][r * 21 + k]; }
    __nv_bfloat16 h, l; splitb(v, h, l);
    g_Wench[idx] = h; g_Wencl[idx] = l;
    if (k == 0) {
        float b = 0.f;
        if (r0 < 1800) { int s = r0 / 300, r = r0 % 300; b = bs[s][r]; }
        g_benc[r0] = b;
    }
}

__global__ void pack_recN(const float* wd, const float* wf, const float* wi,
                          const float* bd, const float* bf, const float* bi,
                          __nv_bfloat16* Wh, __nv_bfloat16* Wl, float* bout)
{
    int idx = blockIdx.x * blockDim.x + threadIdx.x;
    if (idx >= 1024 * 320) return;
    int r0 = idx / 320, k = idx % 320;
    float v = 0.f;
    if (r0 < 900 && k < 300) {
        int g = r0 / 300, r = r0 % 300;
        v = ((g == 0) ? wd : (g == 1) ? wf : wi)[r * 300 + k];
    }
    __nv_bfloat16 h, l; splitb(v, h, l);
    Wh[idx] = h; Wl[idx] = l;
    if (k == 0) {
        float b = 0.f;
        if (r0 < 900) { int g = r0 / 300, r = r0 % 300; b = ((g == 0) ? bd : (g == 1) ? bf : bi)[r]; }
        bout[r0] = b;
    }
}

__global__ void pack_l1N(const float* __restrict__ w)
{
    int idx = blockIdx.x * blockDim.x + threadIdx.x;
    if (idx >= 9 * 128 * 320) return;
    int tap = idx / (128 * 320), rem = idx % (128 * 320);
    int ch = rem / 320, k = rem % 320;
    float v = (k < 300) ? w[ch * 2700 + k * 9 + tap] : 0.f;
    __nv_bfloat16 h, l; splitb(v, h, l);
    g_L1h[idx] = h; g_L1l[idx] = l;
}

__global__ void pack_l2N(const float* __restrict__ w)
{
    int idx = blockIdx.x * blockDim.x + threadIdx.x;
    if (idx >= 128 * 128) return;
    __nv_bfloat16 h, l; splitb(w[idx], h, l);
    g_L2h[idx] = h; g_L2l[idx] = l;
}

__global__ void repack_yN(const float* __restrict__ y)
{
    int idx = blockIdx.x * blockDim.x + threadIdx.x;
    if (idx >= NT * 64) return;
    int n = idx / 64, k = idx % 64;
    float v = 0.f;
    if (k < 21) { int b = n / HW_, p = n % HW_; v = y[(b * 21 + k) * HW_ + p]; }
    __nv_bfloat16 h, l; splitb(v, h, l);
    g_Yxh[idx] = h; g_Yxl[idx] = l;
}

// ---------- elementwise (grid = NT blocks, 320 threads) ----------
__global__ void init_ew()
{
    int n = blockIdx.x, r = threadIdx.x;
    if (r >= 300) return;
    size_t o = (size_t)n * KR + r;
    const float* Er = g_E + (size_t)n * SE;
    float c = sigm_f(Er[900 + r]) * (-Er[r]);
    g_c12f[o] = c;
    float x = fmaxf(c, 0.f);
    __nv_bfloat16 h, l; splitb(x, h, l);
    g_x12h[o] = h; g_x12l[o] = l;
    g_xt1f[o] = 0.f;
}

__global__ void stepA_ew()
{
    int n = blockIdx.x, r = threadIdx.x;
    if (r >= 300) return;
    size_t o = (size_t)n * KR + r;
    const float* Gr = g_G + (size_t)n * SG;
    const float* Er = g_E + (size_t)n * SE;
    float f = sigm_f(Gr[300 + r] + Er[1200 + r]);
    float t = sigm_f(Gr[600 + r] + Er[1500 + r]);
    float ctl = Er[300 + r] + g_xt1f[o] - Gr[r];
    float c = g_c12f[o] * f + ctl * t;
    g_ct1f[o] = c;
    float x = fmaxf(c, 0.f);
    g_xt1f[o] = x;
    __nv_bfloat16 h, l; splitb(x, h, l);
    g_xt1h[o] = h; g_xt1l[o] = l;
}

__global__ void stepB_ew()
{
    int n = blockIdx.x, r = threadIdx.x;
    if (r >= 300) return;
    size_t o = (size_t)n * KR + r;
    const float* Gr = g_G + (size_t)n * SG;
    const float* Er = g_E + (size_t)n * SE;
    float f = sigm_f(Gr[300 + r] + Er[600 + r]);
    float t = sigm_f(Gr[600 + r] + Er[900 + r]);
    float ctl = Er[r] + g_xt1f[o] - Gr[r];
    float c = g_ct1f[o] * f + ctl * t;
    g_c12f[o] = c;
    float x = fmaxf(c, 0.f);
    __nv_bfloat16 h, l; splitb(x, h, l);
    g_x12h[o] = h; g_x12l[o] = l;
}

// ---------- final head ----------
__global__ void head_out(const float* __restrict__ w3, const float* __restrict__ b3,
                         float* __restrict__ out)
{
    int n = blockIdx.x * blockDim.x + threadIdx.x;
    if (n >= NH) return;
    int b = n / HWO, q = n % HWO, i = q / WO, j = q % WO;
    const float* row = g_H2 + (size_t)(b * HW_ + i * W_ + j) * 128;
    float s = b3[0];
#pragma unroll
    for (int c = 0; c < 128; c += 4) {
        float4 h = *(const float4*)(row + c);
        float4 w = *(const float4*)(w3 + c);
        s += h.x * w.x + h.y * w.y + h.z * w.z + h.w * w.w;
    }
    out[n] = s;
}

// ---------- launcher ----------
#define GSA(p, s) cudaGetSymbolAddress((void**)&(p), s)

extern "C" void kernel_launch(void* const* d_in, const int* in_sizes, int n_in,
                              void* d_out, int out_size)
{
    (void)in_sizes; (void)n_in; (void)out_size;
    const float* in[31];
    for (int i = 0; i < 31; i++) in[i] = (const float*)d_in[i];

    static bool attr = false;
    if (!attr) {
        cudaFuncSetAttribute(mma_gemm, cudaFuncAttributeMaxDynamicSharedMemorySize, 81920);
        attr = true;
    }

    float *E, *G, *H2, *benc, *b2, *b1;
    __nv_bfloat16 *Yxh, *Yxl, *Weh, *Wel, *W2h, *W2l, *W1h, *W1l;
    __nv_bfloat16 *x12h, *x12l, *xt1h, *xt1l, *L1h, *L1l, *L2h, *L2l, *H1h, *H1l;
    GSA(E, g_E); GSA(G, g_G); GSA(H2, g_H2);
    GSA(benc, g_benc); GSA(b2, g_b2); GSA(b1, g_b1);
    GSA(Yxh, g_Yxh); GSA(Yxl, g_Yxl);
    GSA(Weh, g_Wench); GSA(Wel, g_Wencl);
    GSA(W2h, g_W2h); GSA(W2l, g_W2l); GSA(W1h, g_W1h); GSA(W1l, g_W1l);
    GSA(x12h, g_x12h); GSA(x12l, g_x12l); GSA(xt1h, g_xt1h); GSA(xt1l, g_xt1l);
    GSA(L1h, g_L1h); GSA(L1l, g_L1l); GSA(L2h, g_L2h); GSA(L2l, g_L2l);
    GSA(H1h, g_H1h); GSA(H1l, g_H1l);

    pack_encN<<<(1920 * 64 + 255) / 256, 256>>>(in[1], in[3], in[5], in[7], in[9], in[11],
                                                in[2], in[4], in[6], in[8], in[10], in[12]);
    pack_recN<<<(1024 * 320 + 255) / 256, 256>>>(in[15], in[21], in[23], in[16], in[22], in[24], W2h, W2l, b2);
    pack_recN<<<(1024 * 320 + 255) / 256, 256>>>(in[13], in[17], in[19], in[14], in[18], in[20], W1h, W1l, b1);
    pack_l1N<<<(9 * 128 * 320 + 255) / 256, 256>>>(in[25]);
    pack_l2N<<<(128 * 128 + 255) / 256, 256>>>(in[27]);
    repack_yN<<<(NT * 64 + 255) / 256, 256>>>(in[0]);

    const int SM = 81920;
    // encoders: E = gelu(Wenc @ Yx + benc)
    mma_gemm<<<dim3(15, PXT), 512, SM>>>(Yxh, Yxl, Weh, Wel, benc, E, 0, 0, 64, 2, 1, 0, SE, 0);
    init_ew<<<NT, 320>>>();

    for (int it = 0; it < 3; it++) {
        mma_gemm<<<dim3(8, PXT), 512, SM>>>(x12h, x12l, W2h, W2l, b2, G, 0, 0, KR, 10, 1, 0, SG, 0);
        stepA_ew<<<NT, 320>>>();
        mma_gemm<<<dim3(8, PXT), 512, SM>>>(xt1h, xt1l, W1h, W1l, b1, G, 0, 0, KR, 10, 1, 0, SG, 0);
        stepB_ew<<<NT, 320>>>();
    }
    mma_gemm<<<dim3(8, PXT), 512, SM>>>(x12h, x12l, W2h, W2l, b2, G, 0, 0, KR, 10, 1, 0, SG, 0);
    stepA_ew<<<NT, 320>>>();

    // head: 3x3 conv as 9 shifted tap-GEMMs on full 144-grid, then 1x1, then dot
    mma_gemm<<<dim3(1, PXT), 512, SM>>>(xt1h, xt1l, L1h, L1l, in[26], 0, H1h, H1l, KR, 10, 9, 1, 128, 1);
    mma_gemm<<<dim3(1, PXT), 512, SM>>>(H1h, H1l, L2h, L2l, in[28], H2, 0, 0, 128, 4, 1, 0, 128, 0);
    head_out<<<(NH + 255) / 256, 256>>>(in[29], in[30], (float*)d_out);
}

// round 6
// speedup vs baseline: 1.8095x; 1.0006x over previous
#include <cuda_runtime.h>
#include <cuda_bf16.h>
#include <math.h>
#include <stdint.h>

constexpr int B_ = 4, H_ = 144, W_ = 144;
constexpr int HW_ = H_ * W_;        // 20736
constexpr int NT  = B_ * HW_;       // 82944 = 648*128
constexpr int HO = 142, WO = 142, HWO = HO * WO, NH = B_ * HWO;
constexpr int PXT = NT / 128;       // 648
constexpr int SE = 1920, SG = 1024, KR = 320;

// ---------- scratch ----------
__device__ float         g_E [ (size_t)NT * SE ];
__device__ float         g_G [ (size_t)NT * SG ];
__device__ float         g_c12f[(size_t)NT * KR];
__device__ float         g_ct1f[(size_t)NT * KR];
__device__ float         g_xt1f[(size_t)NT * KR];
__device__ __nv_bfloat16 g_x12h[(size_t)(NT+512) * KR], g_x12l[(size_t)(NT+512) * KR];
__device__ __nv_bfloat16 g_xt1h[(size_t)(NT+512) * KR], g_xt1l[(size_t)(NT+512) * KR];
__device__ __nv_bfloat16 g_Yxh[(size_t)NT * 64], g_Yxl[(size_t)NT * 64];
__device__ __nv_bfloat16 g_H1h[(size_t)NT * 128], g_H1l[(size_t)NT * 128];
__device__ float         g_H2 [(size_t)NT * 128];
__device__ __nv_bfloat16 g_Wench[1920 * 64], g_Wencl[1920 * 64];
__device__ __nv_bfloat16 g_W2h[1024 * 320], g_W2l[1024 * 320];
__device__ __nv_bfloat16 g_W1h[1024 * 320], g_W1l[1024 * 320];
__device__ __nv_bfloat16 g_L1h[9 * 128 * 320], g_L1l[9 * 128 * 320];
__device__ __nv_bfloat16 g_L2h[128 * 128], g_L2l[128 * 128];
__device__ float g_benc[1920], g_b2[1024], g_b1[1024];

// ---------- helpers ----------
__device__ __forceinline__ uint32_t s2u(const void* p) {
    uint32_t a;
    asm("{ .reg .u64 t; cvta.to.shared.u64 t, %1; cvt.u32.u64 %0, t; }" : "=r"(a) : "l"(p));
    return a;
}
__device__ __forceinline__ float gelu_f(float x) {
    return 0.5f * x * (1.0f + erff(x * 0.70710678118654752440f));
}
__device__ __forceinline__ float sigm_f(float x) { return 1.0f / (1.0f + expf(-x)); }
__device__ __forceinline__ void splitb(float x, __nv_bfloat16& h, __nv_bfloat16& l) {
    h = __float2bfloat16(x);
    l = __float2bfloat16(x - __bfloat162float(h));
}

__device__ __forceinline__ void ldmx4(uint32_t* r, uint32_t addr) {
    asm volatile("ldmatrix.sync.aligned.m8n8.x4.shared.b16 {%0,%1,%2,%3}, [%4];"
                 : "=r"(r[0]), "=r"(r[1]), "=r"(r[2]), "=r"(r[3]) : "r"(addr));
}
__device__ __forceinline__ void hmma(float* c, const uint32_t* a, uint32_t b0, uint32_t b1) {
    asm volatile("mma.sync.aligned.m16n8k16.row.col.f32.bf16.bf16.f32 "
                 "{%0,%1,%2,%3}, {%4,%5,%6,%7}, {%8,%9}, {%0,%1,%2,%3};"
                 : "+f"(c[0]), "+f"(c[1]), "+f"(c[2]), "+f"(c[3])
                 : "r"(a[0]), "r"(a[1]), "r"(a[2]), "r"(a[3]), "r"(b0), "r"(b1));
}

// ================= generic tiled MMA GEMM (bf16x3, mma.sync) =================
// D[128px][128ch] = sum over taps,chunks of A[px+tapOff][k] * B[tap*128+ch][k]
// A rows stride kpad (bf16), B rows stride kpad. chunk K=32, double-buffered.
// smem: 2 stages x 4 matrices (Ah,Al,Bh,Bl) x (128 rows x 80B pitch) = 81920B
__global__ void __launch_bounds__(512, 1)
mma_gemm(const __nv_bfloat16* __restrict__ Ah, const __nv_bfloat16* __restrict__ Al,
         const __nv_bfloat16* __restrict__ Bh, const __nv_bfloat16* __restrict__ Bl,
         const float* __restrict__ bias,
         float* __restrict__ outf, __nv_bfloat16* __restrict__ outh, __nv_bfloat16* __restrict__ outl,
         int kpad, int nchunks, int ntaps, int conv, int ostride, int mode)
{
    extern __shared__ char smem[];
    const uint32_t sb = s2u(smem);
    const int tid = threadIdx.x;
    const int lane = tid & 31, warp = tid >> 5;
    const int wm = warp >> 2, wn = warp & 3;
    const int ch0 = blockIdx.x * 128;
    const int n0  = blockIdx.y * 128;

    const int ldRow = tid >> 2, ldC = tid & 3;

    // ldmatrix lane address pieces (stage-relative)
    const uint32_t aOff = (uint32_t)((wm * 32 + (lane & 15)) * 80 + (lane >> 4) * 16);
    const uint32_t bOff = (uint32_t)((wn * 32 + ((lane >> 4) & 1) * 8 + (lane & 7)) * 80
                                     + ((lane >> 3) & 1) * 16);

    float acc[2][4][4];
#pragma unroll
    for (int i = 0; i < 2; i++)
#pragma unroll
        for (int j = 0; j < 4; j++)
#pragma unroll
            for (int q = 0; q < 4; q++) acc[i][j][q] = 0.f;

    const int total = ntaps * nchunks;

    // ---- prologue: load chunk 0 into stage 0 ----
    {
        long long ao = (long long)(n0 + ldRow) * kpad + ldC * 8;
        long long bo = (long long)(ch0 + ldRow) * kpad + ldC * 8;
        char* st = smem + ldRow * 80 + ldC * 16;
        *(uint4*)(st        ) = *(const uint4*)(Ah + ao);
        *(uint4*)(st + 10240) = *(const uint4*)(Al + ao);
        *(uint4*)(st + 20480) = *(const uint4*)(Bh + bo);
        *(uint4*)(st + 30720) = *(const uint4*)(Bl + bo);
    }
    __syncthreads();

    for (int tc = 0; tc < total; tc++) {
        const int stage = tc & 1;
        uint4 pf[4];
        const bool more = (tc + 1) < total;
        if (more) {
            int t1 = tc + 1;
            int tap = t1 / nchunks, chunk = t1 - tap * nchunks;
            int tapOff = conv ? ((tap / 3) * 144 + (tap % 3)) : 0;
            int brow0  = conv ? tap * 128 : 0;
            long long k0 = (long long)chunk * 32;
            long long ao = (long long)(n0 + ldRow + tapOff) * kpad + k0 + ldC * 8;
            long long bo = (long long)(brow0 + ch0 + ldRow) * kpad + k0 + ldC * 8;
            pf[0] = *(const uint4*)(Ah + ao);
            pf[1] = *(const uint4*)(Al + ao);
            pf[2] = *(const uint4*)(Bh + bo);
            pf[3] = *(const uint4*)(Bl + bo);
        }

        // ---- compute this stage: 2 k16 steps ----
        const uint32_t sbase = sb + stage * 40960;
#pragma unroll
        for (int kb = 0; kb < 2; kb++) {
            uint32_t ah[2][4], al[2][4], bh[2][4], bl[2][4];
#pragma unroll
            for (int mt = 0; mt < 2; mt++) {
                uint32_t ad = sbase + kb * 32 + mt * 1280 + aOff;
                ldmx4(ah[mt], ad);
                ldmx4(al[mt], ad + 10240);
            }
#pragma unroll
            for (int np = 0; np < 2; np++) {
                uint32_t bd = sbase + 20480 + kb * 32 + np * 1280 + bOff;
                ldmx4(bh[np], bd);
                ldmx4(bl[np], bd + 10240);
            }
#pragma unroll
            for (int mt = 0; mt < 2; mt++)
#pragma unroll
                for (int nt = 0; nt < 4; nt++) {
                    const int np = nt >> 1, q = (nt & 1) * 2;
                    hmma(acc[mt][nt], ah[mt], bh[np][q], bh[np][q + 1]);
                    hmma(acc[mt][nt], ah[mt], bl[np][q], bl[np][q + 1]);
                    hmma(acc[mt][nt], al[mt], bh[np][q], bh[np][q + 1]);
                }
        }

        if (more) {
            char* st = smem + (stage ^ 1) * 40960 + ldRow * 80 + ldC * 16;
            *(uint4*)(st        ) = pf[0];
            *(uint4*)(st + 10240) = pf[1];
            *(uint4*)(st + 20480) = pf[2];
            *(uint4*)(st + 30720) = pf[3];
            __syncthreads();
        }
    }

    // ---- epilogue ----
    const int rbase = n0 + wm * 32 + (lane >> 2);
    const int cbase = ch0 + wn * 32 + (lane & 3) * 2;
#pragma unroll
    for (int mt = 0; mt < 2; mt++)
#pragma unroll
        for (int nt = 0; nt < 4; nt++) {
            const int col = cbase + nt * 8;
            const float b0 = bias[col], b1 = bias[col + 1];
#pragma unroll
            for (int half = 0; half < 2; half++) {
                const long long row = rbase + mt * 16 + half * 8;
                float v0 = gelu_f(acc[mt][nt][half * 2 + 0] + b0);
                float v1 = gelu_f(acc[mt][nt][half * 2 + 1] + b1);
                if (mode == 0) {
                    float2 v = make_float2(v0, v1);
                    *(float2*)(outf + row * ostride + col) = v;
                } else {
                    __nv_bfloat16 h0, l0, h1, l1;
                    splitb(v0, h0, l0);
                    splitb(v1, h1, l1);
                    uint32_t ph = (uint32_t)__bfloat16_as_ushort(h0) |
                                  ((uint32_t)__bfloat16_as_ushort(h1) << 16);
                    uint32_t pl = (uint32_t)__bfloat16_as_ushort(l0) |
                                  ((uint32_t)__bfloat16_as_ushort(l1) << 16);
                    *(uint32_t*)(outh + row * ostride + col) = ph;
                    *(uint32_t*)(outl + row * ostride + col) = pl;
                }
            }
        }
}

// ---------- packs ----------
__global__ void pack_encN(const float* w0, const float* w1, const float* w2,
                          const float* w3, const float* w4, const float* w5,
                          const float* b0, const float* b1, const float* b2,
                          const float* b3, const float* b4, const float* b5)
{
    int idx = blockIdx.x * blockDim.x + threadIdx.x;
    if (idx >= 1920 * 64) return;
    const float* ws[6] = {w0, w1, w2, w3, w4, w5};
    const float* bs[6] = {b0, b1, b2, b3, b4, b5};
    int r0 = idx / 64, k = idx % 64;
    float v = 0.f;
    if (r0 < 1800 && k < 21) { int s = r0 / 300, r = r0 % 300; v = ws[s][r * 21 + k]; }
    __nv_bfloat16 h, l; splitb(v, h, l);
    g_Wench[idx] = h; g_Wencl[idx] = l;
    if (k == 0) {
        float b = 0.f;
        if (r0 < 1800) { int s = r0 / 300, r = r0 % 300; b = bs[s][r]; }
        g_benc[r0] = b;
    }
}

__global__ void pack_recN(const float* wd, const float* wf, const float* wi,
                          const float* bd, const float* bf, const float* bi,
                          __nv_bfloat16* Wh, __nv_bfloat16* Wl, float* bout)
{
    int idx = blockIdx.x * blockDim.x + threadIdx.x;
    if (idx >= 1024 * 320) return;
    int r0 = idx / 320, k = idx % 320;
    float v = 0.f;
    if (r0 < 900 && k < 300) {
        int g = r0 / 300, r = r0 % 300;
        v = ((g == 0) ? wd : (g == 1) ? wf : wi)[r * 300 + k];
    }
    __nv_bfloat16 h, l; splitb(v, h, l);
    Wh[idx] = h; Wl[idx] = l;
    if (k == 0) {
        float b = 0.f;
        if (r0 < 900) { int g = r0 / 300, r = r0 % 300; b = ((g == 0) ? bd : (g == 1) ? bf : bi)[r]; }
        bout[r0] = b;
    }
}

__global__ void pack_l1N(const float* __restrict__ w)
{
    int idx = blockIdx.x * blockDim.x + threadIdx.x;
    if (idx >= 9 * 128 * 320) return;
    int tap = idx / (128 * 320), rem = idx % (128 * 320);
    int ch = rem / 320, k = rem % 320;
    float v = (k < 300) ? w[ch * 2700 + k * 9 + tap] : 0.f;
    __nv_bfloat16 h, l; splitb(v, h, l);
    g_L1h[idx] = h; g_L1l[idx] = l;
}

__global__ void pack_l2N(const float* __restrict__ w)
{
    int idx = blockIdx.x * blockDim.x + threadIdx.x;
    if (idx >= 128 * 128) return;
    __nv_bfloat16 h, l; splitb(w[idx], h, l);
    g_L2h[idx] = h; g_L2l[idx] = l;
}

__global__ void repack_yN(const float* __restrict__ y)
{
    int idx = blockIdx.x * blockDim.x + threadIdx.x;
    if (idx >= NT * 64) return;
    int n = idx / 64, k = idx % 64;
    float v = 0.f;
    if (k < 21) { int b = n / HW_, p = n % HW_; v = y[(b * 21 + k) * HW_ + p]; }
    __nv_bfloat16 h, l; splitb(v, h, l);
    g_Yxh[idx] = h; g_Yxl[idx] = l;
}

// ---------- elementwise (grid = NT blocks, 320 threads) ----------
__global__ void init_ew()
{
    int n = blockIdx.x, r = threadIdx.x;
    if (r >= 300) return;
    size_t o = (size_t)n * KR + r;
    const float* Er = g_E + (size_t)n * SE;
    float c = sigm_f(Er[900 + r]) * (-Er[r]);
    g_c12f[o] = c;
    float x = fmaxf(c, 0.f);
    __nv_bfloat16 h, l; splitb(x, h, l);
    g_x12h[o] = h; g_x12l[o] = l;
    g_xt1f[o] = 0.f;
}

__global__ void stepA_ew()
{
    int n = blockIdx.x, r = threadIdx.x;
    if (r >= 300) return;
    size_t o = (size_t)n * KR + r;
    const float* Gr = g_G + (size_t)n * SG;
    const float* Er = g_E + (size_t)n * SE;
    float f = sigm_f(Gr[300 + r] + Er[1200 + r]);
    float t = sigm_f(Gr[600 + r] + Er[1500 + r]);
    float ctl = Er[300 + r] + g_xt1f[o] - Gr[r];
    float c = g_c12f[o] * f + ctl * t;
    g_ct1f[o] = c;
    float x = fmaxf(c, 0.f);
    g_xt1f[o] = x;
    __nv_bfloat16 h, l; splitb(x, h, l);
    g_xt1h[o] = h; g_xt1l[o] = l;
}

__global__ void stepB_ew()
{
    int n = blockIdx.x, r = threadIdx.x;
    if (r >= 300) return;
    size_t o = (size_t)n * KR + r;
    const float* Gr = g_G + (size_t)n * SG;
    const float* Er = g_E + (size_t)n * SE;
    float f = sigm_f(Gr[300 + r] + Er[600 + r]);
    float t = sigm_f(Gr[600 + r] + Er[900 + r]);
    float ctl = Er[r] + g_xt1f[o] - Gr[r];
    float c = g_ct1f[o] * f + ctl * t;
    g_c12f[o] = c;
    float x = fmaxf(c, 0.f);
    __nv_bfloat16 h, l; splitb(x, h, l);
    g_x12h[o] = h; g_x12l[o] = l;
}

// ---------- final head ----------
__global__ void head_out(const float* __restrict__ w3, const float* __restrict__ b3,
                         float* __restrict__ out)
{
    int n = blockIdx.x * blockDim.x + threadIdx.x;
    if (n >= NH) return;
    int b = n / HWO, q = n % HWO, i = q / WO, j = q % WO;
    const float* row = g_H2 + (size_t)(b * HW_ + i * W_ + j) * 128;
    float s = b3[0];
#pragma unroll
    for (int c = 0; c < 128; c += 4) {
        float4 h = *(const float4*)(row + c);
        float4 w = *(const float4*)(w3 + c);
        s += h.x * w.x + h.y * w.y + h.z * w.z + h.w * w.w;
    }
    out[n] = s;
}

// ---------- launcher ----------
#define GSA(p, s) cudaGetSymbolAddress((void**)&(p), s)

extern "C" void kernel_launch(void* const* d_in, const int* in_sizes, int n_in,
                              void* d_out, int out_size)
{
    (void)in_sizes; (void)n_in; (void)out_size;
    const float* in[31];
    for (int i = 0; i < 31; i++) in[i] = (const float*)d_in[i];

    static bool attr = false;
    if (!attr) {
        cudaFuncSetAttribute(mma_gemm, cudaFuncAttributeMaxDynamicSharedMemorySize, 81920);
        attr = true;
    }

    float *E, *G, *H2, *benc, *b2, *b1;
    __nv_bfloat16 *Yxh, *Yxl, *Weh, *Wel, *W2h, *W2l, *W1h, *W1l;
    __nv_bfloat16 *x12h, *x12l, *xt1h, *xt1l, *L1h, *L1l, *L2h, *L2l, *H1h, *H1l;
    GSA(E, g_E); GSA(G, g_G); GSA(H2, g_H2);
    GSA(benc, g_benc); GSA(b2, g_b2); GSA(b1, g_b1);
    GSA(Yxh, g_Yxh); GSA(Yxl, g_Yxl);
    GSA(Weh, g_Wench); GSA(Wel, g_Wencl);
    GSA(W2h, g_W2h); GSA(W2l, g_W2l); GSA(W1h, g_W1h); GSA(W1l, g_W1l);
    GSA(x12h, g_x12h); GSA(x12l, g_x12l); GSA(xt1h, g_xt1h); GSA(xt1l, g_xt1l);
    GSA(L1h, g_L1h); GSA(L1l, g_L1l); GSA(L2h, g_L2h); GSA(L2l, g_L2l);
    GSA(H1h, g_H1h); GSA(H1l, g_H1l);

    pack_encN<<<(1920 * 64 + 255) / 256, 256>>>(in[1], in[3], in[5], in[7], in[9], in[11],
                                                in[2], in[4], in[6], in[8], in[10], in[12]);
    pack_recN<<<(1024 * 320 + 255) / 256, 256>>>(in[15], in[21], in[23], in[16], in[22], in[24], W2h, W2l, b2);
    pack_recN<<<(1024 * 320 + 255) / 256, 256>>>(in[13], in[17], in[19], in[14], in[18], in[20], W1h, W1l, b1);
    pack_l1N<<<(9 * 128 * 320 + 255) / 256, 256>>>(in[25]);
    pack_l2N<<<(128 * 128 + 255) / 256, 256>>>(in[27]);
    repack_yN<<<(NT * 64 + 255) / 256, 256>>>(in[0]);

    const int SM = 81920;
    // encoders: E = gelu(Wenc @ Yx + benc)
    mma_gemm<<<dim3(15, PXT), 512, SM>>>(Yxh, Yxl, Weh, Wel, benc, E, 0, 0, 64, 2, 1, 0, SE, 0);
    init_ew<<<NT, 320>>>();

    for (int it = 0; it < 3; it++) {
        mma_gemm<<<dim3(8, PXT), 512, SM>>>(x12h, x12l, W2h, W2l, b2, G, 0, 0, KR, 10, 1, 0, SG, 0);
        stepA_ew<<<NT, 320>>>();
        mma_gemm<<<dim3(8, PXT), 512, SM>>>(xt1h, xt1l, W1h, W1l, b1, G, 0, 0, KR, 10, 1, 0, SG, 0);
        stepB_ew<<<NT, 320>>>();
    }
    mma_gemm<<<dim3(8, PXT), 512, SM>>>(x12h, x12l, W2h, W2l, b2, G, 0, 0, KR, 10, 1, 0, SG, 0);
    stepA_ew<<<NT, 320>>>();

    // head: 3x3 conv as 9 shifted tap-GEMMs on full 144-grid, then 1x1, then dot
    mma_gemm<<<dim3(1, PXT), 512, SM>>>(xt1h, xt1l, L1h, L1l, in[26], 0, H1h, H1l, KR, 10, 9, 1, 128, 1);
    mma_gemm<<<dim3(1, PXT), 512, SM>>>(H1h, H1l, L2h, L2l, in[28], H2, 0, 0, 128, 4, 1, 0, 128, 0);
    head_out<<<(NH + 255) / 256, 256>>>(in[29], in[30], (float*)d_out);
}